// round 2
// baseline (speedup 1.0000x reference)
#include <cuda_runtime.h>
#include <cstdint>

// Problem constants
#define B_SZ   8
#define T_SEQ  1024
#define C_DIM  768
#define H_NUM  12
#define D_DIM  64
#define M_ROWS (B_SZ * T_SEQ)          // 8192
#define N_QKV  (3 * C_DIM)             // 2304
#define SOFTMAX_SCALE 0.125f           // 1/sqrt(64)

// Scratch (allocation-free rule: __device__ globals)
__device__ float g_qkv[(size_t)M_ROWS * N_QKV];   // [8192, 2304]
__device__ float g_y[(size_t)M_ROWS * C_DIM];     // [8192, 768]

// ---------------------------------------------------------------------------
// Tiled SGEMM with bias: C[M,N] = A[M,K] * B[K,N] + bias[N]
// BM=BN=128, BK=16, 256 threads, 8x8 microtile per thread.
// Requires M%128==0, N%128==0, K%16==0 (true for all our shapes: K=768).
// ---------------------------------------------------------------------------
__global__ __launch_bounds__(256, 2)
void sgemm_bias_kernel(const float* __restrict__ A,
                       const float* __restrict__ B,
                       const float* __restrict__ bias,
                       float* __restrict__ C,
                       int M, int N, int K)
{
    constexpr int BM = 128, BN = 128, BK = 16, TM = 8, TN = 8;
    __shared__ float As[BK][BM];
    __shared__ float Bs[BK][BN];

    const int tid  = threadIdx.x;            // 0..255
    const int brow = blockIdx.y;
    const int bcol = blockIdx.x;

    const float* Ablk = A + (size_t)brow * BM * K;
    const float* Bblk = B + (size_t)bcol * BN;

    // A tile load mapping: 128 rows x 16 cols -> two float4 per thread
    //   each thread loads rows tid>>1 (stride 128 over 2 sub-cols of 8)
    const int a_row = tid >> 2;              // 0..63 (two rows per thread: +0, +64)
    const int a_col = (tid & 3) * 4;         // 0,4,8,12
    // B tile load mapping: 16 rows x 128 cols -> two float4 per thread
    const int b_row = tid >> 5;              // 0..7 (two rows: +0, +8)
    const int b_col = (tid & 31) * 4;        // 0..124

    const int trow = (tid >> 4) * TM;        // 0..120
    const int tcol = (tid & 15) * TN;        // 0..120

    float acc[TM][TN];
    #pragma unroll
    for (int i = 0; i < TM; i++)
        #pragma unroll
        for (int j = 0; j < TN; j++)
            acc[i][j] = 0.0f;

    for (int k0 = 0; k0 < K; k0 += BK) {
        // Load A: rows a_row and a_row+64, cols [k0+a_col, k0+a_col+4)
        float4 av0 = *(const float4*)(Ablk + (size_t)(a_row)      * K + k0 + a_col);
        float4 av1 = *(const float4*)(Ablk + (size_t)(a_row + 64) * K + k0 + a_col);
        // Load B: rows k0+b_row and k0+b_row+8, cols [b_col, b_col+4)
        float4 bv0 = *(const float4*)(Bblk + (size_t)(k0 + b_row)     * N + b_col);
        float4 bv1 = *(const float4*)(Bblk + (size_t)(k0 + b_row + 8) * N + b_col);

        As[a_col + 0][a_row] = av0.x;
        As[a_col + 1][a_row] = av0.y;
        As[a_col + 2][a_row] = av0.z;
        As[a_col + 3][a_row] = av0.w;
        As[a_col + 0][a_row + 64] = av1.x;
        As[a_col + 1][a_row + 64] = av1.y;
        As[a_col + 2][a_row + 64] = av1.z;
        As[a_col + 3][a_row + 64] = av1.w;
        *(float4*)&Bs[b_row][b_col]     = bv0;
        *(float4*)&Bs[b_row + 8][b_col] = bv1;
        __syncthreads();

        #pragma unroll
        for (int k = 0; k < BK; k++) {
            float a[TM], b[TN];
            #pragma unroll
            for (int i = 0; i < TM; i += 4) {
                float4 v = *(const float4*)&As[k][trow + i];
                a[i] = v.x; a[i+1] = v.y; a[i+2] = v.z; a[i+3] = v.w;
            }
            #pragma unroll
            for (int j = 0; j < TN; j += 4) {
                float4 v = *(const float4*)&Bs[k][tcol + j];
                b[j] = v.x; b[j+1] = v.y; b[j+2] = v.z; b[j+3] = v.w;
            }
            #pragma unroll
            for (int i = 0; i < TM; i++)
                #pragma unroll
                for (int j = 0; j < TN; j++)
                    acc[i][j] += a[i] * b[j];
        }
        __syncthreads();
    }

    // Epilogue: bias + store
    #pragma unroll
    for (int i = 0; i < TM; i++) {
        const size_t row = (size_t)brow * BM + trow + i;
        #pragma unroll
        for (int j = 0; j < TN; j += 4) {
            const int col = bcol * BN + tcol + j;
            float4 v;
            v.x = acc[i][j + 0] + bias[col + 0];
            v.y = acc[i][j + 1] + bias[col + 1];
            v.z = acc[i][j + 2] + bias[col + 2];
            v.w = acc[i][j + 3] + bias[col + 3];
            *(float4*)(C + row * N + col) = v;
        }
    }
}

// ---------------------------------------------------------------------------
// Causal flash attention. One thread per query row.
// Block: 128 threads = 128 queries for one (b, h). Grid: (T/128, B*H).
// qkv layout: [B*T, 3C] with q at col h*64, k at C + h*64, v at 2C + h*64.
// Output y: [B*T, C] at col h*64 (head-interleaved, row-major for proj GEMM).
// ---------------------------------------------------------------------------
__global__ __launch_bounds__(128, 2)
void attn_kernel(const float* __restrict__ qkv, float* __restrict__ y)
{
    constexpr int QB = 128;   // queries per block
    constexpr int KB = 64;    // keys per smem tile

    const int bh    = blockIdx.y;            // 0..95
    const int b     = bh / H_NUM;
    const int h     = bh % H_NUM;
    const int qtile = blockIdx.x;            // 0..7
    const int tid   = threadIdx.x;           // 0..127
    const int q_idx = qtile * QB + tid;      // global query position in sequence

    __shared__ float Ks[KB][D_DIM];
    __shared__ float Vs[KB][D_DIM];

    const float* base = qkv + (size_t)b * T_SEQ * N_QKV + h * D_DIM;

    // Load this thread's q row into registers
    float qreg[D_DIM];
    {
        const float* qp = base + (size_t)q_idx * N_QKV;
        #pragma unroll
        for (int d4 = 0; d4 < D_DIM / 4; d4++) {
            float4 v = *(const float4*)(qp + d4 * 4);
            qreg[d4*4+0] = v.x; qreg[d4*4+1] = v.y;
            qreg[d4*4+2] = v.z; qreg[d4*4+3] = v.w;
        }
    }

    float m = -1e30f;
    float l = 0.0f;
    float acc[D_DIM];
    #pragma unroll
    for (int d = 0; d < D_DIM; d++) acc[d] = 0.0f;

    const int n_kt = qtile * 2 + 2;   // key tiles needed: ceil((qtile*128+128)/64)

    for (int kt = 0; kt < n_kt; kt++) {
        __syncthreads();   // protect smem reuse from previous iteration
        // Cooperative K/V tile load: 64 rows x 16 float4 each
        for (int idx = tid; idx < KB * (D_DIM / 4); idx += 128) {
            const int r  = idx >> 4;          // key row in tile
            const int c4 = idx & 15;          // float4 column
            const int tk = kt * KB + r;
            const float* kp = base + (size_t)tk * N_QKV + C_DIM;
            const float* vp = base + (size_t)tk * N_QKV + 2 * C_DIM;
            *(float4*)&Ks[r][c4 * 4] = *(const float4*)(kp + c4 * 4);
            *(float4*)&Vs[r][c4 * 4] = *(const float4*)(vp + c4 * 4);
        }
        __syncthreads();

        const bool tile_unmasked = (kt * KB + KB - 1) <= q_idx;

        // Process keys in chunks of 16 to amortize the rescale
        #pragma unroll
        for (int j0 = 0; j0 < KB; j0 += 16) {
            float s[16];
            float mc = -1e30f;
            #pragma unroll
            for (int j = 0; j < 16; j++) {
                const int kk = kt * KB + j0 + j;
                float dot = 0.0f;
                #pragma unroll
                for (int d4 = 0; d4 < D_DIM / 4; d4++) {
                    float4 kv = *(const float4*)&Ks[j0 + j][d4 * 4];
                    dot += qreg[d4*4+0] * kv.x;
                    dot += qreg[d4*4+1] * kv.y;
                    dot += qreg[d4*4+2] * kv.z;
                    dot += qreg[d4*4+3] * kv.w;
                }
                s[j] = (tile_unmasked || kk <= q_idx) ? dot * SOFTMAX_SCALE : -1e30f;
                mc = fmaxf(mc, s[j]);
            }
            const float m_new = fmaxf(m, mc);
            const float corr = __expf(m - m_new);
            m = m_new;
            l *= corr;
            #pragma unroll
            for (int d = 0; d < D_DIM; d++) acc[d] *= corr;
            #pragma unroll
            for (int j = 0; j < 16; j++) {
                const float p = __expf(s[j] - m);
                l += p;
                #pragma unroll
                for (int d4 = 0; d4 < D_DIM / 4; d4++) {
                    float4 vv = *(const float4*)&Vs[j0 + j][d4 * 4];
                    acc[d4*4+0] += p * vv.x;
                    acc[d4*4+1] += p * vv.y;
                    acc[d4*4+2] += p * vv.z;
                    acc[d4*4+3] += p * vv.w;
                }
            }
        }
    }

    const float inv_l = 1.0f / l;
    float* yp = y + (size_t)(b * T_SEQ + q_idx) * C_DIM + h * D_DIM;
    #pragma unroll
    for (int d4 = 0; d4 < D_DIM / 4; d4++) {
        float4 v;
        v.x = acc[d4*4+0] * inv_l;
        v.y = acc[d4*4+1] * inv_l;
        v.z = acc[d4*4+2] * inv_l;
        v.w = acc[d4*4+3] * inv_l;
        *(float4*)(yp + d4 * 4) = v;
    }
}

// ---------------------------------------------------------------------------
// Launch
// ---------------------------------------------------------------------------
extern "C" void kernel_launch(void* const* d_in, const int* in_sizes, int n_in,
                              void* d_out, int out_size)
{
    const float* x      = (const float*)d_in[0];   // [8, 1024, 768]
    const float* W_attn = (const float*)d_in[1];   // [768, 2304]
    const float* b_attn = (const float*)d_in[2];   // [2304]
    const float* W_proj = (const float*)d_in[3];   // [768, 768]
    const float* b_proj = (const float*)d_in[4];   // [768]
    float* out = (float*)d_out;                    // [8, 1024, 768]

    float* qkv;  cudaGetSymbolAddress((void**)&qkv, g_qkv);
    float* ybuf; cudaGetSymbolAddress((void**)&ybuf, g_y);

    // 1) QKV GEMM: [8192,768] x [768,2304] + bias
    {
        dim3 grid(N_QKV / 128, M_ROWS / 128);   // (18, 64)
        sgemm_bias_kernel<<<grid, 256>>>(x, W_attn, b_attn, qkv,
                                         M_ROWS, N_QKV, C_DIM);
    }
    // 2) Causal flash attention
    {
        dim3 grid(T_SEQ / 128, B_SZ * H_NUM);   // (8, 96)
        attn_kernel<<<grid, 128>>>(qkv, ybuf);
    }
    // 3) Projection GEMM: [8192,768] x [768,768] + bias
    {
        dim3 grid(C_DIM / 128, M_ROWS / 128);   // (6, 64)
        sgemm_bias_kernel<<<grid, 256>>>(ybuf, W_proj, b_proj, out,
                                         M_ROWS, C_DIM, C_DIM);
    }
}

// round 3
// speedup vs baseline: 1.0589x; 1.0589x over previous
#include <cuda_runtime.h>
#include <cstdint>

// Problem constants
#define B_SZ   8
#define T_SEQ  1024
#define C_DIM  768
#define H_NUM  12
#define D_DIM  64
#define M_ROWS (B_SZ * T_SEQ)          // 8192
#define N_QKV  (3 * C_DIM)             // 2304
#define SOFTMAX_SCALE 0.125f           // 1/sqrt(64)

// Scratch (allocation-free rule: __device__ globals)
__device__ float g_qkv[(size_t)M_ROWS * N_QKV];   // [8192, 2304]
__device__ float g_y[(size_t)M_ROWS * C_DIM];     // [8192, 768]

// ---------------------------------------------------------------------------
// Tiled SGEMM with bias: C[M,N] = A[M,K] * B[K,N] + bias[N]
// BM=BN=128, BK=16, 256 threads, 8x8 microtile, single-stage gmem prefetch.
// Requires M%128==0, N%128==0, K%16==0.
// ---------------------------------------------------------------------------
__global__ __launch_bounds__(256, 2)
void sgemm_bias_kernel(const float* __restrict__ A,
                       const float* __restrict__ B,
                       const float* __restrict__ bias,
                       float* __restrict__ C,
                       int M, int N, int K)
{
    constexpr int BM = 128, BN = 128, BK = 16, TM = 8, TN = 8;
    __shared__ float As[BK][BM];
    __shared__ float Bs[BK][BN];

    const int tid  = threadIdx.x;            // 0..255
    const int brow = blockIdx.y;
    const int bcol = blockIdx.x;

    const float* Ablk = A + (size_t)brow * BM * K;
    const float* Bblk = B + (size_t)bcol * BN;

    const int a_row = tid >> 2;              // 0..63 (rows +0, +64)
    const int a_col = (tid & 3) * 4;         // 0,4,8,12
    const int b_row = tid >> 5;              // 0..7 (rows +0, +8)
    const int b_col = (tid & 31) * 4;        // 0..124

    const int trow = (tid >> 4) * TM;        // 0..120
    const int tcol = (tid & 15) * TN;        // 0..120

    float acc[TM][TN];
    #pragma unroll
    for (int i = 0; i < TM; i++)
        #pragma unroll
        for (int j = 0; j < TN; j++)
            acc[i][j] = 0.0f;

    // Prefetch first tile
    float4 av0 = *(const float4*)(Ablk + (size_t)(a_row)      * K + a_col);
    float4 av1 = *(const float4*)(Ablk + (size_t)(a_row + 64) * K + a_col);
    float4 bv0 = *(const float4*)(Bblk + (size_t)(b_row)     * N + b_col);
    float4 bv1 = *(const float4*)(Bblk + (size_t)(b_row + 8) * N + b_col);

    for (int k0 = 0; k0 < K; k0 += BK) {
        // Commit current prefetch to smem
        As[a_col + 0][a_row] = av0.x;
        As[a_col + 1][a_row] = av0.y;
        As[a_col + 2][a_row] = av0.z;
        As[a_col + 3][a_row] = av0.w;
        As[a_col + 0][a_row + 64] = av1.x;
        As[a_col + 1][a_row + 64] = av1.y;
        As[a_col + 2][a_row + 64] = av1.z;
        As[a_col + 3][a_row + 64] = av1.w;
        *(float4*)&Bs[b_row][b_col]     = bv0;
        *(float4*)&Bs[b_row + 8][b_col] = bv1;
        __syncthreads();

        // Issue next-tile gmem loads early (overlap with FMA loop)
        const int kn = k0 + BK;
        if (kn < K) {
            av0 = *(const float4*)(Ablk + (size_t)(a_row)      * K + kn + a_col);
            av1 = *(const float4*)(Ablk + (size_t)(a_row + 64) * K + kn + a_col);
            bv0 = *(const float4*)(Bblk + (size_t)(kn + b_row)     * N + b_col);
            bv1 = *(const float4*)(Bblk + (size_t)(kn + b_row + 8) * N + b_col);
        }

        #pragma unroll
        for (int k = 0; k < BK; k++) {
            float a[TM], b[TN];
            #pragma unroll
            for (int i = 0; i < TM; i += 4) {
                float4 v = *(const float4*)&As[k][trow + i];
                a[i] = v.x; a[i+1] = v.y; a[i+2] = v.z; a[i+3] = v.w;
            }
            #pragma unroll
            for (int j = 0; j < TN; j += 4) {
                float4 v = *(const float4*)&Bs[k][tcol + j];
                b[j] = v.x; b[j+1] = v.y; b[j+2] = v.z; b[j+3] = v.w;
            }
            #pragma unroll
            for (int i = 0; i < TM; i++)
                #pragma unroll
                for (int j = 0; j < TN; j++)
                    acc[i][j] += a[i] * b[j];
        }
        __syncthreads();
    }

    // Epilogue: bias + store
    #pragma unroll
    for (int i = 0; i < TM; i++) {
        const size_t row = (size_t)brow * BM + trow + i;
        #pragma unroll
        for (int j = 0; j < TN; j += 4) {
            const int col = bcol * BN + tcol + j;
            float4 v;
            v.x = acc[i][j + 0] + bias[col + 0];
            v.y = acc[i][j + 1] + bias[col + 1];
            v.z = acc[i][j + 2] + bias[col + 2];
            v.w = acc[i][j + 3] + bias[col + 3];
            *(float4*)(C + row * N + col) = v;
        }
    }
}

// ---------------------------------------------------------------------------
// Causal flash attention, split-D: 2 threads per query, each owns half of D.
// Block: 128 threads = 64 queries for one (b, h). Grid: (T/64, B*H).
// Thread t: query = qtile*64 + (t>>1), half = t&1 (D slice [half*32, half*32+32)).
// Dot products are combined across the pair with one shfl.xor.
// qkv layout: [B*T, 3C] q @ h*64, k @ C+h*64, v @ 2C+h*64.
// ---------------------------------------------------------------------------
__global__ __launch_bounds__(128, 4)
void attn_kernel(const float* __restrict__ qkv, float* __restrict__ y)
{
    constexpr int QB = 64;    // queries per block
    constexpr int KB = 64;    // keys per smem tile
    constexpr int HD = 32;    // half of head dim per thread

    const int bh    = blockIdx.y;                  // 0..95
    const int b     = bh / H_NUM;
    const int h     = bh % H_NUM;
    // Reverse order: heaviest q-tiles (longest key range) launch first.
    const int qtile = (gridDim.x - 1) - blockIdx.x;  // 0..15
    const int tid   = threadIdx.x;                 // 0..127
    const int q_loc = tid >> 1;                    // 0..63
    const int half  = tid & 1;                     // 0 or 1
    const int q_idx = qtile * QB + q_loc;          // global query position

    __shared__ float Ks[KB][D_DIM];
    __shared__ float Vs[KB][D_DIM];

    const float* base = qkv + (size_t)b * T_SEQ * N_QKV + h * D_DIM;

    // Load this thread's half-q row into registers
    float qreg[HD];
    {
        const float* qp = base + (size_t)q_idx * N_QKV + half * HD;
        #pragma unroll
        for (int d4 = 0; d4 < HD / 4; d4++) {
            float4 v = *(const float4*)(qp + d4 * 4);
            qreg[d4*4+0] = v.x; qreg[d4*4+1] = v.y;
            qreg[d4*4+2] = v.z; qreg[d4*4+3] = v.w;
        }
    }

    float m = -1e30f;
    float l = 0.0f;
    float acc[HD];
    #pragma unroll
    for (int d = 0; d < HD; d++) acc[d] = 0.0f;

    const int n_kt = qtile + 1;   // key tiles: ceil((qtile*64+64)/64)

    for (int kt = 0; kt < n_kt; kt++) {
        __syncthreads();   // protect smem reuse from previous iteration
        // Cooperative K/V tile load: 64 rows x 16 float4 each (2048 float4)
        for (int idx = tid; idx < KB * (D_DIM / 4); idx += 128) {
            const int r  = idx >> 4;          // key row in tile
            const int c4 = idx & 15;          // float4 column
            const int tk = kt * KB + r;
            const float* kp = base + (size_t)tk * N_QKV + C_DIM;
            const float* vp = base + (size_t)tk * N_QKV + 2 * C_DIM;
            *(float4*)&Ks[r][c4 * 4] = *(const float4*)(kp + c4 * 4);
            *(float4*)&Vs[r][c4 * 4] = *(const float4*)(vp + c4 * 4);
        }
        __syncthreads();

        const bool tile_unmasked = (kt * KB + KB - 1) <= q_idx;

        // Process keys in chunks of 16 to amortize the rescale
        #pragma unroll
        for (int j0 = 0; j0 < KB; j0 += 16) {
            float s[16];
            float mc = -1e30f;
            #pragma unroll
            for (int j = 0; j < 16; j++) {
                const int kk = kt * KB + j0 + j;
                float dot = 0.0f;
                #pragma unroll
                for (int d4 = 0; d4 < HD / 4; d4++) {
                    float4 kv = *(const float4*)&Ks[j0 + j][half * HD + d4 * 4];
                    dot += qreg[d4*4+0] * kv.x;
                    dot += qreg[d4*4+1] * kv.y;
                    dot += qreg[d4*4+2] * kv.z;
                    dot += qreg[d4*4+3] * kv.w;
                }
                // Combine the two halves of the dot product across the pair
                dot += __shfl_xor_sync(0xffffffffu, dot, 1);
                s[j] = (tile_unmasked || kk <= q_idx) ? dot * SOFTMAX_SCALE : -1e30f;
                mc = fmaxf(mc, s[j]);
            }
            const float m_new = fmaxf(m, mc);
            const float corr = __expf(m - m_new);
            m = m_new;
            l *= corr;
            #pragma unroll
            for (int d = 0; d < HD; d++) acc[d] *= corr;
            #pragma unroll
            for (int j = 0; j < 16; j++) {
                const float p = __expf(s[j] - m);
                l += p;
                #pragma unroll
                for (int d4 = 0; d4 < HD / 4; d4++) {
                    float4 vv = *(const float4*)&Vs[j0 + j][half * HD + d4 * 4];
                    acc[d4*4+0] += p * vv.x;
                    acc[d4*4+1] += p * vv.y;
                    acc[d4*4+2] += p * vv.z;
                    acc[d4*4+3] += p * vv.w;
                }
            }
        }
    }

    const float inv_l = 1.0f / l;   // both halves computed identical l
    float* yp = y + (size_t)(b * T_SEQ + q_idx) * C_DIM + h * D_DIM + half * HD;
    #pragma unroll
    for (int d4 = 0; d4 < HD / 4; d4++) {
        float4 v;
        v.x = acc[d4*4+0] * inv_l;
        v.y = acc[d4*4+1] * inv_l;
        v.z = acc[d4*4+2] * inv_l;
        v.w = acc[d4*4+3] * inv_l;
        *(float4*)(yp + d4 * 4) = v;
    }
}

// ---------------------------------------------------------------------------
// Launch
// ---------------------------------------------------------------------------
extern "C" void kernel_launch(void* const* d_in, const int* in_sizes, int n_in,
                              void* d_out, int out_size)
{
    const float* x      = (const float*)d_in[0];   // [8, 1024, 768]
    const float* W_attn = (const float*)d_in[1];   // [768, 2304]
    const float* b_attn = (const float*)d_in[2];   // [2304]
    const float* W_proj = (const float*)d_in[3];   // [768, 768]
    const float* b_proj = (const float*)d_in[4];   // [768]
    float* out = (float*)d_out;                    // [8, 1024, 768]

    float* qkv;  cudaGetSymbolAddress((void**)&qkv, g_qkv);
    float* ybuf; cudaGetSymbolAddress((void**)&ybuf, g_y);

    // 1) QKV GEMM: [8192,768] x [768,2304] + bias
    {
        dim3 grid(N_QKV / 128, M_ROWS / 128);   // (18, 64)
        sgemm_bias_kernel<<<grid, 256>>>(x, W_attn, b_attn, qkv,
                                         M_ROWS, N_QKV, C_DIM);
    }
    // 2) Causal flash attention (split-D pairs)
    {
        dim3 grid(T_SEQ / 64, B_SZ * H_NUM);    // (16, 96)
        attn_kernel<<<grid, 128>>>(qkv, ybuf);
    }
    // 3) Projection GEMM: [8192,768] x [768,768] + bias
    {
        dim3 grid(C_DIM / 128, M_ROWS / 128);   // (6, 64)
        sgemm_bias_kernel<<<grid, 256>>>(ybuf, W_proj, b_proj, out,
                                         M_ROWS, C_DIM, C_DIM);
    }
}

// round 4
// speedup vs baseline: 1.5747x; 1.4871x over previous
#include <cuda_runtime.h>
#include <cstdint>

// Problem constants
#define B_SZ   8
#define T_SEQ  1024
#define C_DIM  768
#define H_NUM  12
#define D_DIM  64
#define M_ROWS (B_SZ * T_SEQ)          // 8192
#define N_QKV  (3 * C_DIM)             // 2304
#define SOFTMAX_SCALE 0.125f           // 1/sqrt(64)

// Scratch (allocation-free rule: __device__ globals)
__device__ float g_qkv[(size_t)M_ROWS * N_QKV];   // [8192, 2304]
__device__ float g_y[(size_t)M_ROWS * C_DIM];     // [8192, 768]

// ---------------------------------------------------------------------------
// TF32 tensor-core GEMM with bias: C[M,N] = A[M,K] * B[K,N] + bias[N]
// mma.sync.aligned.m16n8k8.row.col.f32.tf32.tf32.f32
// BM=BN=128, BK=16, 256 threads (8 warps, 2x4), warp tile 64x32 (4x4 frags).
// Requires M%128==0, N%128==0, K%16==0.
// ---------------------------------------------------------------------------
__device__ __forceinline__ uint32_t f2tf32(float x) {
    uint32_t r;
    asm("cvt.rna.tf32.f32 %0, %1;" : "=r"(r) : "f"(x));
    return r;
}

__device__ __forceinline__ void mma_tf32(float c[4],
                                         uint32_t a0, uint32_t a1,
                                         uint32_t a2, uint32_t a3,
                                         uint32_t b0, uint32_t b1) {
    asm volatile(
        "mma.sync.aligned.m16n8k8.row.col.f32.tf32.tf32.f32 "
        "{%0,%1,%2,%3}, {%4,%5,%6,%7}, {%8,%9}, {%0,%1,%2,%3};\n"
        : "+f"(c[0]), "+f"(c[1]), "+f"(c[2]), "+f"(c[3])
        : "r"(a0), "r"(a1), "r"(a2), "r"(a3), "r"(b0), "r"(b1));
}

__global__ __launch_bounds__(256, 2)
void gemm_tf32_bias_kernel(const float* __restrict__ A,
                           const float* __restrict__ B,
                           const float* __restrict__ bias,
                           float* __restrict__ C,
                           int M, int N, int K)
{
    constexpr int BM = 128, BN = 128, BK = 16;
    constexpr int LDA = 136;   // smem stride (floats) -> conflict-free frag loads
    constexpr int LDB = 136;

    __shared__ uint32_t As[BK][LDA];   // [k][m], tf32 bits
    __shared__ uint32_t Bs[BK][LDB];   // [k][n], tf32 bits

    const int tid  = threadIdx.x;            // 0..255
    const int brow = blockIdx.y;
    const int bcol = blockIdx.x;

    const int warp = tid >> 5;               // 0..7
    const int lane = tid & 31;
    const int g    = lane >> 2;              // group 0..7
    const int t    = lane & 3;               // thread-in-group 0..3
    const int wm   = (warp & 1) * 64;        // warp m offset (2 warps in m)
    const int wn   = (warp >> 1) * 32;       // warp n offset (4 warps in n)

    const float* Ablk = A + (size_t)brow * BM * K;
    const float* Bblk = B + (size_t)bcol * BN;

    // gmem load mapping (same shape as before)
    const int a_row = tid >> 2;              // 0..63 (rows +0, +64)
    const int a_col = (tid & 3) * 4;         // 0,4,8,12
    const int b_row = tid >> 5;              // 0..7 (rows +0, +8)
    const int b_col = (tid & 31) * 4;        // 0..124

    float c[4][4][4];                        // [mt][nt][frag]
    #pragma unroll
    for (int mt = 0; mt < 4; mt++)
        #pragma unroll
        for (int nt = 0; nt < 4; nt++)
            #pragma unroll
            for (int i = 0; i < 4; i++)
                c[mt][nt][i] = 0.0f;

    // Prefetch first tile
    float4 av0 = *(const float4*)(Ablk + (size_t)(a_row)      * K + a_col);
    float4 av1 = *(const float4*)(Ablk + (size_t)(a_row + 64) * K + a_col);
    float4 bv0 = *(const float4*)(Bblk + (size_t)(b_row)     * N + b_col);
    float4 bv1 = *(const float4*)(Bblk + (size_t)(b_row + 8) * N + b_col);

    for (int k0 = 0; k0 < K; k0 += BK) {
        // Commit prefetch to smem (A transposed to [k][m]), converting to tf32
        As[a_col + 0][a_row]      = f2tf32(av0.x);
        As[a_col + 1][a_row]      = f2tf32(av0.y);
        As[a_col + 2][a_row]      = f2tf32(av0.z);
        As[a_col + 3][a_row]      = f2tf32(av0.w);
        As[a_col + 0][a_row + 64] = f2tf32(av1.x);
        As[a_col + 1][a_row + 64] = f2tf32(av1.y);
        As[a_col + 2][a_row + 64] = f2tf32(av1.z);
        As[a_col + 3][a_row + 64] = f2tf32(av1.w);
        Bs[b_row][b_col + 0]      = f2tf32(bv0.x);
        Bs[b_row][b_col + 1]      = f2tf32(bv0.y);
        Bs[b_row][b_col + 2]      = f2tf32(bv0.z);
        Bs[b_row][b_col + 3]      = f2tf32(bv0.w);
        Bs[b_row + 8][b_col + 0]  = f2tf32(bv1.x);
        Bs[b_row + 8][b_col + 1]  = f2tf32(bv1.y);
        Bs[b_row + 8][b_col + 2]  = f2tf32(bv1.z);
        Bs[b_row + 8][b_col + 3]  = f2tf32(bv1.w);
        __syncthreads();

        // Prefetch next tile during MMA work
        const int kn = k0 + BK;
        if (kn < K) {
            av0 = *(const float4*)(Ablk + (size_t)(a_row)      * K + kn + a_col);
            av1 = *(const float4*)(Ablk + (size_t)(a_row + 64) * K + kn + a_col);
            bv0 = *(const float4*)(Bblk + (size_t)(kn + b_row)     * N + b_col);
            bv1 = *(const float4*)(Bblk + (size_t)(kn + b_row + 8) * N + b_col);
        }

        // Two k-steps of 8
        #pragma unroll
        for (int ks = 0; ks < BK; ks += 8) {
            uint32_t a[4][4], bf[4][2];
            #pragma unroll
            for (int mt = 0; mt < 4; mt++) {
                const int m = wm + mt * 16 + g;
                a[mt][0] = As[ks + t][m];
                a[mt][1] = As[ks + t][m + 8];
                a[mt][2] = As[ks + t + 4][m];
                a[mt][3] = As[ks + t + 4][m + 8];
            }
            #pragma unroll
            for (int nt = 0; nt < 4; nt++) {
                const int n = wn + nt * 8 + g;
                bf[nt][0] = Bs[ks + t][n];
                bf[nt][1] = Bs[ks + t + 4][n];
            }
            #pragma unroll
            for (int mt = 0; mt < 4; mt++)
                #pragma unroll
                for (int nt = 0; nt < 4; nt++)
                    mma_tf32(c[mt][nt],
                             a[mt][0], a[mt][1], a[mt][2], a[mt][3],
                             bf[nt][0], bf[nt][1]);
        }
        __syncthreads();
    }

    // Epilogue: bias + store (fragment layout: c0 (g, 2t), c1 (g, 2t+1),
    // c2 (g+8, 2t), c3 (g+8, 2t+1))
    #pragma unroll
    for (int mt = 0; mt < 4; mt++) {
        #pragma unroll
        for (int nt = 0; nt < 4; nt++) {
            const int col = bcol * BN + wn + nt * 8 + 2 * t;
            const float bx = bias[col];
            const float by = bias[col + 1];
            const size_t row0 = (size_t)brow * BM + wm + mt * 16 + g;
            float2 v0 = make_float2(c[mt][nt][0] + bx, c[mt][nt][1] + by);
            float2 v1 = make_float2(c[mt][nt][2] + bx, c[mt][nt][3] + by);
            *(float2*)(C + row0 * N + col)       = v0;
            *(float2*)(C + (row0 + 8) * N + col) = v1;
        }
    }
}

// ---------------------------------------------------------------------------
// Causal flash attention, split-D: 2 threads per query, each owns half of D.
// (unchanged from round 3)
// ---------------------------------------------------------------------------
__global__ __launch_bounds__(128, 4)
void attn_kernel(const float* __restrict__ qkv, float* __restrict__ y)
{
    constexpr int QB = 64;    // queries per block
    constexpr int KB = 64;    // keys per smem tile
    constexpr int HD = 32;    // half of head dim per thread

    const int bh    = blockIdx.y;                  // 0..95
    const int b     = bh / H_NUM;
    const int h     = bh % H_NUM;
    const int qtile = (gridDim.x - 1) - blockIdx.x;  // heavy tiles first
    const int tid   = threadIdx.x;                 // 0..127
    const int q_loc = tid >> 1;                    // 0..63
    const int half  = tid & 1;                     // 0 or 1
    const int q_idx = qtile * QB + q_loc;          // global query position

    __shared__ float Ks[KB][D_DIM];
    __shared__ float Vs[KB][D_DIM];

    const float* base = qkv + (size_t)b * T_SEQ * N_QKV + h * D_DIM;

    float qreg[HD];
    {
        const float* qp = base + (size_t)q_idx * N_QKV + half * HD;
        #pragma unroll
        for (int d4 = 0; d4 < HD / 4; d4++) {
            float4 v = *(const float4*)(qp + d4 * 4);
            qreg[d4*4+0] = v.x; qreg[d4*4+1] = v.y;
            qreg[d4*4+2] = v.z; qreg[d4*4+3] = v.w;
        }
    }

    float m = -1e30f;
    float l = 0.0f;
    float acc[HD];
    #pragma unroll
    for (int d = 0; d < HD; d++) acc[d] = 0.0f;

    const int n_kt = qtile + 1;

    for (int kt = 0; kt < n_kt; kt++) {
        __syncthreads();
        for (int idx = tid; idx < KB * (D_DIM / 4); idx += 128) {
            const int r  = idx >> 4;
            const int c4 = idx & 15;
            const int tk = kt * KB + r;
            const float* kp = base + (size_t)tk * N_QKV + C_DIM;
            const float* vp = base + (size_t)tk * N_QKV + 2 * C_DIM;
            *(float4*)&Ks[r][c4 * 4] = *(const float4*)(kp + c4 * 4);
            *(float4*)&Vs[r][c4 * 4] = *(const float4*)(vp + c4 * 4);
        }
        __syncthreads();

        const bool tile_unmasked = (kt * KB + KB - 1) <= q_idx;

        #pragma unroll
        for (int j0 = 0; j0 < KB; j0 += 16) {
            float s[16];
            float mc = -1e30f;
            #pragma unroll
            for (int j = 0; j < 16; j++) {
                const int kk = kt * KB + j0 + j;
                float dot = 0.0f;
                #pragma unroll
                for (int d4 = 0; d4 < HD / 4; d4++) {
                    float4 kv = *(const float4*)&Ks[j0 + j][half * HD + d4 * 4];
                    dot += qreg[d4*4+0] * kv.x;
                    dot += qreg[d4*4+1] * kv.y;
                    dot += qreg[d4*4+2] * kv.z;
                    dot += qreg[d4*4+3] * kv.w;
                }
                dot += __shfl_xor_sync(0xffffffffu, dot, 1);
                s[j] = (tile_unmasked || kk <= q_idx) ? dot * SOFTMAX_SCALE : -1e30f;
                mc = fmaxf(mc, s[j]);
            }
            const float m_new = fmaxf(m, mc);
            const float corr = __expf(m - m_new);
            m = m_new;
            l *= corr;
            #pragma unroll
            for (int d = 0; d < HD; d++) acc[d] *= corr;
            #pragma unroll
            for (int j = 0; j < 16; j++) {
                const float p = __expf(s[j] - m);
                l += p;
                #pragma unroll
                for (int d4 = 0; d4 < HD / 4; d4++) {
                    float4 vv = *(const float4*)&Vs[j0 + j][half * HD + d4 * 4];
                    acc[d4*4+0] += p * vv.x;
                    acc[d4*4+1] += p * vv.y;
                    acc[d4*4+2] += p * vv.z;
                    acc[d4*4+3] += p * vv.w;
                }
            }
        }
    }

    const float inv_l = 1.0f / l;
    float* yp = y + (size_t)(b * T_SEQ + q_idx) * C_DIM + h * D_DIM + half * HD;
    #pragma unroll
    for (int d4 = 0; d4 < HD / 4; d4++) {
        float4 v;
        v.x = acc[d4*4+0] * inv_l;
        v.y = acc[d4*4+1] * inv_l;
        v.z = acc[d4*4+2] * inv_l;
        v.w = acc[d4*4+3] * inv_l;
        *(float4*)(yp + d4 * 4) = v;
    }
}

// ---------------------------------------------------------------------------
// Launch
// ---------------------------------------------------------------------------
extern "C" void kernel_launch(void* const* d_in, const int* in_sizes, int n_in,
                              void* d_out, int out_size)
{
    const float* x      = (const float*)d_in[0];   // [8, 1024, 768]
    const float* W_attn = (const float*)d_in[1];   // [768, 2304]
    const float* b_attn = (const float*)d_in[2];   // [2304]
    const float* W_proj = (const float*)d_in[3];   // [768, 768]
    const float* b_proj = (const float*)d_in[4];   // [768]
    float* out = (float*)d_out;                    // [8, 1024, 768]

    float* qkv;  cudaGetSymbolAddress((void**)&qkv, g_qkv);
    float* ybuf; cudaGetSymbolAddress((void**)&ybuf, g_y);

    // 1) QKV GEMM (TF32 tensor cores): [8192,768] x [768,2304] + bias
    {
        dim3 grid(N_QKV / 128, M_ROWS / 128);   // (18, 64)
        gemm_tf32_bias_kernel<<<grid, 256>>>(x, W_attn, b_attn, qkv,
                                             M_ROWS, N_QKV, C_DIM);
    }
    // 2) Causal flash attention (split-D pairs)
    {
        dim3 grid(T_SEQ / 64, B_SZ * H_NUM);    // (16, 96)
        attn_kernel<<<grid, 128>>>(qkv, ybuf);
    }
    // 3) Projection GEMM (TF32 tensor cores): [8192,768] x [768,768] + bias
    {
        dim3 grid(C_DIM / 128, M_ROWS / 128);   // (6, 64)
        gemm_tf32_bias_kernel<<<grid, 256>>>(ybuf, W_proj, b_proj, out,
                                             M_ROWS, C_DIM, C_DIM);
    }
}

// round 6
// speedup vs baseline: 4.1209x; 2.6170x over previous
#include <cuda_runtime.h>
#include <cstdint>

// Problem constants
#define B_SZ   8
#define T_SEQ  1024
#define C_DIM  768
#define H_NUM  12
#define D_DIM  64
#define M_ROWS (B_SZ * T_SEQ)          // 8192
#define N_QKV  (3 * C_DIM)             // 2304
#define SOFTMAX_SCALE 0.125f           // 1/sqrt(64), exact power of two

// Scratch (allocation-free rule: __device__ globals)
__device__ float g_qkv[(size_t)M_ROWS * N_QKV];   // [8192, 2304]
__device__ float g_y[(size_t)M_ROWS * C_DIM];     // [8192, 768]

// ---------------------------------------------------------------------------
// TF32 helpers
// ---------------------------------------------------------------------------
__device__ __forceinline__ uint32_t f2tf32(float x) {
    uint32_t r;
    asm("cvt.rna.tf32.f32 %0, %1;" : "=r"(r) : "f"(x));
    return r;
}

__device__ __forceinline__ void mma_tf32(float c[4],
                                         uint32_t a0, uint32_t a1,
                                         uint32_t a2, uint32_t a3,
                                         uint32_t b0, uint32_t b1) {
    asm volatile(
        "mma.sync.aligned.m16n8k8.row.col.f32.tf32.tf32.f32 "
        "{%0,%1,%2,%3}, {%4,%5,%6,%7}, {%8,%9}, {%0,%1,%2,%3};\n"
        : "+f"(c[0]), "+f"(c[1]), "+f"(c[2]), "+f"(c[3])
        : "r"(a0), "r"(a1), "r"(a2), "r"(a3), "r"(b0), "r"(b1));
}

// ---------------------------------------------------------------------------
// TF32 tensor-core GEMM with bias (unchanged)
// ---------------------------------------------------------------------------
__global__ __launch_bounds__(256, 2)
void gemm_tf32_bias_kernel(const float* __restrict__ A,
                           const float* __restrict__ B,
                           const float* __restrict__ bias,
                           float* __restrict__ C,
                           int M, int N, int K)
{
    constexpr int BM = 128, BN = 128, BK = 16;
    constexpr int LDA = 136;
    constexpr int LDB = 136;

    __shared__ uint32_t As[BK][LDA];   // [k][m], tf32 bits
    __shared__ uint32_t Bs[BK][LDB];   // [k][n], tf32 bits

    const int tid  = threadIdx.x;
    const int brow = blockIdx.y;
    const int bcol = blockIdx.x;

    const int warp = tid >> 5;
    const int lane = tid & 31;
    const int g    = lane >> 2;
    const int t    = lane & 3;
    const int wm   = (warp & 1) * 64;
    const int wn   = (warp >> 1) * 32;

    const float* Ablk = A + (size_t)brow * BM * K;
    const float* Bblk = B + (size_t)bcol * BN;

    const int a_row = tid >> 2;
    const int a_col = (tid & 3) * 4;
    const int b_row = tid >> 5;
    const int b_col = (tid & 31) * 4;

    float c[4][4][4];
    #pragma unroll
    for (int mt = 0; mt < 4; mt++)
        #pragma unroll
        for (int nt = 0; nt < 4; nt++)
            #pragma unroll
            for (int i = 0; i < 4; i++)
                c[mt][nt][i] = 0.0f;

    float4 av0 = *(const float4*)(Ablk + (size_t)(a_row)      * K + a_col);
    float4 av1 = *(const float4*)(Ablk + (size_t)(a_row + 64) * K + a_col);
    float4 bv0 = *(const float4*)(Bblk + (size_t)(b_row)     * N + b_col);
    float4 bv1 = *(const float4*)(Bblk + (size_t)(b_row + 8) * N + b_col);

    for (int k0 = 0; k0 < K; k0 += BK) {
        As[a_col + 0][a_row]      = f2tf32(av0.x);
        As[a_col + 1][a_row]      = f2tf32(av0.y);
        As[a_col + 2][a_row]      = f2tf32(av0.z);
        As[a_col + 3][a_row]      = f2tf32(av0.w);
        As[a_col + 0][a_row + 64] = f2tf32(av1.x);
        As[a_col + 1][a_row + 64] = f2tf32(av1.y);
        As[a_col + 2][a_row + 64] = f2tf32(av1.z);
        As[a_col + 3][a_row + 64] = f2tf32(av1.w);
        Bs[b_row][b_col + 0]      = f2tf32(bv0.x);
        Bs[b_row][b_col + 1]      = f2tf32(bv0.y);
        Bs[b_row][b_col + 2]      = f2tf32(bv0.z);
        Bs[b_row][b_col + 3]      = f2tf32(bv0.w);
        Bs[b_row + 8][b_col + 0]  = f2tf32(bv1.x);
        Bs[b_row + 8][b_col + 1]  = f2tf32(bv1.y);
        Bs[b_row + 8][b_col + 2]  = f2tf32(bv1.z);
        Bs[b_row + 8][b_col + 3]  = f2tf32(bv1.w);
        __syncthreads();

        const int kn = k0 + BK;
        if (kn < K) {
            av0 = *(const float4*)(Ablk + (size_t)(a_row)      * K + kn + a_col);
            av1 = *(const float4*)(Ablk + (size_t)(a_row + 64) * K + kn + a_col);
            bv0 = *(const float4*)(Bblk + (size_t)(kn + b_row)     * N + b_col);
            bv1 = *(const float4*)(Bblk + (size_t)(kn + b_row + 8) * N + b_col);
        }

        #pragma unroll
        for (int ks = 0; ks < BK; ks += 8) {
            uint32_t a[4][4], bf[4][2];
            #pragma unroll
            for (int mt = 0; mt < 4; mt++) {
                const int m = wm + mt * 16 + g;
                a[mt][0] = As[ks + t][m];
                a[mt][1] = As[ks + t][m + 8];
                a[mt][2] = As[ks + t + 4][m];
                a[mt][3] = As[ks + t + 4][m + 8];
            }
            #pragma unroll
            for (int nt = 0; nt < 4; nt++) {
                const int n = wn + nt * 8 + g;
                bf[nt][0] = Bs[ks + t][n];
                bf[nt][1] = Bs[ks + t + 4][n];
            }
            #pragma unroll
            for (int mt = 0; mt < 4; mt++)
                #pragma unroll
                for (int nt = 0; nt < 4; nt++)
                    mma_tf32(c[mt][nt],
                             a[mt][0], a[mt][1], a[mt][2], a[mt][3],
                             bf[nt][0], bf[nt][1]);
        }
        __syncthreads();
    }

    #pragma unroll
    for (int mt = 0; mt < 4; mt++) {
        #pragma unroll
        for (int nt = 0; nt < 4; nt++) {
            const int col = bcol * BN + wn + nt * 8 + 2 * t;
            const float bx = bias[col];
            const float by = bias[col + 1];
            const size_t row0 = (size_t)brow * BM + wm + mt * 16 + g;
            float2 v0 = make_float2(c[mt][nt][0] + bx, c[mt][nt][1] + by);
            float2 v1 = make_float2(c[mt][nt][2] + bx, c[mt][nt][3] + by);
            *(float2*)(C + row0 * N + col)       = v0;
            *(float2*)(C + (row0 + 8) * N + col) = v1;
        }
    }
}

// ---------------------------------------------------------------------------
// Tensor-core causal flash attention (TF32 m16n8k8).
// Block: 128 threads (4 warps), Q tile 64, KV tile 64. Grid: (T/64, B*H).
// FIX vs round 5: row sums (l) are now quad-reduced like the row maxima.
// ---------------------------------------------------------------------------
#define SQ 68
#define SV 72
#define ATT_SMEM_BYTES ((64 * SQ * 3 + 64 * SV) * 4)   // 70656

__global__ __launch_bounds__(128)
void attn_mma_kernel(const float* __restrict__ qkv, float* __restrict__ y)
{
    extern __shared__ uint32_t sm[];
    uint32_t* Qs = sm;                   // [64][SQ]
    uint32_t* Ks = Qs + 64 * SQ;         // [64][SQ]
    uint32_t* Vs = Ks + 64 * SQ;         // [64][SV]
    uint32_t* Ps = Vs + 64 * SV;         // [64][SQ]

    const int bh    = blockIdx.y;                    // 0..95
    const int b     = bh / H_NUM;
    const int h     = bh % H_NUM;
    const int qtile = (gridDim.x - 1) - blockIdx.x;  // heavy tiles first
    const int tid   = threadIdx.x;
    const int warp  = tid >> 5;
    const int lane  = tid & 31;
    const int g     = lane >> 2;                     // 0..7
    const int t     = lane & 3;                      // 0..3
    const int q0    = qtile * 64;

    const float* base = qkv + (size_t)b * T_SEQ * N_QKV + h * D_DIM;

    // Load Q tile (pre-scaled; 0.125 is a power of two -> lossless in tf32)
    for (int idx = tid; idx < 64 * 16; idx += 128) {
        const int r  = idx >> 4;
        const int c4 = (idx & 15) * 4;
        float4 v = *(const float4*)(base + (size_t)(q0 + r) * N_QKV + c4);
        Qs[r * SQ + c4 + 0] = f2tf32(v.x * SOFTMAX_SCALE);
        Qs[r * SQ + c4 + 1] = f2tf32(v.y * SOFTMAX_SCALE);
        Qs[r * SQ + c4 + 2] = f2tf32(v.z * SOFTMAX_SCALE);
        Qs[r * SQ + c4 + 3] = f2tf32(v.w * SOFTMAX_SCALE);
    }

    const int qr = warp * 16;       // warp's first local q row
    const int qa = q0 + qr + g;     // global query row (fragment row 0)
    const int qb = qa + 8;          // global query row (fragment row 1)

    float m0 = -1e30f, m1 = -1e30f, l0 = 0.0f, l1 = 0.0f;
    float O[8][4];
    #pragma unroll
    for (int n = 0; n < 8; n++)
        #pragma unroll
        for (int i = 0; i < 4; i++)
            O[n][i] = 0.0f;

    for (int kt = 0; kt <= qtile; kt++) {
        __syncthreads();
        // Load K/V tiles (natural [key][d] layout, converted to tf32)
        const float* kbase = base + (size_t)kt * 64 * N_QKV;
        for (int idx = tid; idx < 64 * 16; idx += 128) {
            const int r  = idx >> 4;
            const int c4 = (idx & 15) * 4;
            float4 kv = *(const float4*)(kbase + (size_t)r * N_QKV + C_DIM + c4);
            float4 vv = *(const float4*)(kbase + (size_t)r * N_QKV + 2 * C_DIM + c4);
            Ks[r * SQ + c4 + 0] = f2tf32(kv.x);
            Ks[r * SQ + c4 + 1] = f2tf32(kv.y);
            Ks[r * SQ + c4 + 2] = f2tf32(kv.z);
            Ks[r * SQ + c4 + 3] = f2tf32(kv.w);
            Vs[r * SV + c4 + 0] = f2tf32(vv.x);
            Vs[r * SV + c4 + 1] = f2tf32(vv.y);
            Vs[r * SV + c4 + 2] = f2tf32(vv.z);
            Vs[r * SV + c4 + 3] = f2tf32(vv.w);
        }
        __syncthreads();

        // S = Q * K^T   (16x64 per warp; accumulate over D in 8 k-steps)
        float s[8][4];
        #pragma unroll
        for (int n = 0; n < 8; n++)
            #pragma unroll
            for (int i = 0; i < 4; i++)
                s[n][i] = 0.0f;

        #pragma unroll
        for (int ks = 0; ks < 8; ks++) {
            const uint32_t a0 = Qs[(qr + g)     * SQ + ks * 8 + t];
            const uint32_t a1 = Qs[(qr + g + 8) * SQ + ks * 8 + t];
            const uint32_t a2 = Qs[(qr + g)     * SQ + ks * 8 + t + 4];
            const uint32_t a3 = Qs[(qr + g + 8) * SQ + ks * 8 + t + 4];
            #pragma unroll
            for (int nt = 0; nt < 8; nt++) {
                // B = K^T: element (k=d, n=key) = Ks[key][d]
                const uint32_t b0 = Ks[(nt * 8 + g) * SQ + ks * 8 + t];
                const uint32_t b1 = Ks[(nt * 8 + g) * SQ + ks * 8 + t + 4];
                mma_tf32(s[nt], a0, a1, a2, a3, b0, b1);
            }
        }

        // Causal mask (only the diagonal tile)
        if (kt == qtile) {
            #pragma unroll
            for (int nt = 0; nt < 8; nt++) {
                const int kc = kt * 64 + nt * 8 + 2 * t;
                if (kc     > qa) s[nt][0] = -1e30f;
                if (kc + 1 > qa) s[nt][1] = -1e30f;
                if (kc     > qb) s[nt][2] = -1e30f;
                if (kc + 1 > qb) s[nt][3] = -1e30f;
            }
        }

        // Online softmax: row maxima (quad-reduce), rescale, exp, write P
        float mc0 = -1e30f, mc1 = -1e30f;
        #pragma unroll
        for (int nt = 0; nt < 8; nt++) {
            mc0 = fmaxf(mc0, fmaxf(s[nt][0], s[nt][1]));
            mc1 = fmaxf(mc1, fmaxf(s[nt][2], s[nt][3]));
        }
        mc0 = fmaxf(mc0, __shfl_xor_sync(0xffffffffu, mc0, 1));
        mc0 = fmaxf(mc0, __shfl_xor_sync(0xffffffffu, mc0, 2));
        mc1 = fmaxf(mc1, __shfl_xor_sync(0xffffffffu, mc1, 1));
        mc1 = fmaxf(mc1, __shfl_xor_sync(0xffffffffu, mc1, 2));

        const float mn0 = fmaxf(m0, mc0);
        const float mn1 = fmaxf(m1, mc1);
        const float cr0 = __expf(m0 - mn0);
        const float cr1 = __expf(m1 - mn1);
        m0 = mn0; m1 = mn1;

        float pl0 = 0.0f, pl1 = 0.0f;
        #pragma unroll
        for (int nt = 0; nt < 8; nt++) {
            const float p0 = __expf(s[nt][0] - m0);
            const float p1 = __expf(s[nt][1] - m0);
            const float p2 = __expf(s[nt][2] - m1);
            const float p3 = __expf(s[nt][3] - m1);
            pl0 += p0 + p1;
            pl1 += p2 + p3;
            const int col = nt * 8 + 2 * t;
            Ps[(qr + g)     * SQ + col]     = f2tf32(p0);
            Ps[(qr + g)     * SQ + col + 1] = f2tf32(p1);
            Ps[(qr + g + 8) * SQ + col]     = f2tf32(p2);
            Ps[(qr + g + 8) * SQ + col + 1] = f2tf32(p3);
        }
        // FIX: reduce the row sums across the quad (was missing -> NaN/wrong)
        pl0 += __shfl_xor_sync(0xffffffffu, pl0, 1);
        pl0 += __shfl_xor_sync(0xffffffffu, pl0, 2);
        pl1 += __shfl_xor_sync(0xffffffffu, pl1, 1);
        pl1 += __shfl_xor_sync(0xffffffffu, pl1, 2);

        l0 = l0 * cr0 + pl0;
        l1 = l1 * cr1 + pl1;
        #pragma unroll
        for (int n = 0; n < 8; n++) {
            O[n][0] *= cr0; O[n][1] *= cr0;
            O[n][2] *= cr1; O[n][3] *= cr1;
        }
        __syncwarp();   // P rows are warp-private; quad cross-reads below

        // O += P * V  (k-dim = keys, 8 k-steps)
        #pragma unroll
        for (int ks = 0; ks < 8; ks++) {
            const uint32_t a0 = Ps[(qr + g)     * SQ + ks * 8 + t];
            const uint32_t a1 = Ps[(qr + g + 8) * SQ + ks * 8 + t];
            const uint32_t a2 = Ps[(qr + g)     * SQ + ks * 8 + t + 4];
            const uint32_t a3 = Ps[(qr + g + 8) * SQ + ks * 8 + t + 4];
            #pragma unroll
            for (int nt2 = 0; nt2 < 8; nt2++) {
                const uint32_t b0 = Vs[(ks * 8 + t)     * SV + nt2 * 8 + g];
                const uint32_t b1 = Vs[(ks * 8 + t + 4) * SV + nt2 * 8 + g];
                mma_tf32(O[nt2], a0, a1, a2, a3, b0, b1);
            }
        }
    }

    // Epilogue: normalize and store
    const float i0 = 1.0f / l0;
    const float i1 = 1.0f / l1;
    float* ya = y + ((size_t)b * T_SEQ + qa) * C_DIM + h * D_DIM;
    float* yb = y + ((size_t)b * T_SEQ + qb) * C_DIM + h * D_DIM;
    #pragma unroll
    for (int nt2 = 0; nt2 < 8; nt2++) {
        const int d = nt2 * 8 + 2 * t;
        *(float2*)(ya + d) = make_float2(O[nt2][0] * i0, O[nt2][1] * i0);
        *(float2*)(yb + d) = make_float2(O[nt2][2] * i1, O[nt2][3] * i1);
    }
}

// ---------------------------------------------------------------------------
// Launch
// ---------------------------------------------------------------------------
extern "C" void kernel_launch(void* const* d_in, const int* in_sizes, int n_in,
                              void* d_out, int out_size)
{
    const float* x      = (const float*)d_in[0];   // [8, 1024, 768]
    const float* W_attn = (const float*)d_in[1];   // [768, 2304]
    const float* b_attn = (const float*)d_in[2];   // [2304]
    const float* W_proj = (const float*)d_in[3];   // [768, 768]
    const float* b_proj = (const float*)d_in[4];   // [768]
    float* out = (float*)d_out;                    // [8, 1024, 768]

    float* qkv;  cudaGetSymbolAddress((void**)&qkv, g_qkv);
    float* ybuf; cudaGetSymbolAddress((void**)&ybuf, g_y);

    cudaFuncSetAttribute(attn_mma_kernel,
                         cudaFuncAttributeMaxDynamicSharedMemorySize,
                         ATT_SMEM_BYTES);

    // 1) QKV GEMM (TF32 tensor cores): [8192,768] x [768,2304] + bias
    {
        dim3 grid(N_QKV / 128, M_ROWS / 128);   // (18, 64)
        gemm_tf32_bias_kernel<<<grid, 256>>>(x, W_attn, b_attn, qkv,
                                             M_ROWS, N_QKV, C_DIM);
    }
    // 2) Causal flash attention (TF32 tensor cores)
    {
        dim3 grid(T_SEQ / 64, B_SZ * H_NUM);    // (16, 96)
        attn_mma_kernel<<<grid, 128, ATT_SMEM_BYTES>>>(qkv, ybuf);
    }
    // 3) Projection GEMM (TF32 tensor cores): [8192,768] x [768,768] + bias
    {
        dim3 grid(C_DIM / 128, M_ROWS / 128);   // (6, 64)
        gemm_tf32_bias_kernel<<<grid, 256>>>(ybuf, W_proj, b_proj, out,
                                             M_ROWS, C_DIM, C_DIM);
    }
}

// round 7
// speedup vs baseline: 4.4754x; 1.0860x over previous
#include <cuda_runtime.h>
#include <cstdint>

// Problem constants
#define B_SZ   8
#define T_SEQ  1024
#define C_DIM  768
#define H_NUM  12
#define D_DIM  64
#define M_ROWS (B_SZ * T_SEQ)          // 8192
#define N_QKV  (3 * C_DIM)             // 2304
#define SOFTMAX_SCALE 0.125f           // 1/sqrt(64), exact power of two

// Scratch (allocation-free rule: __device__ globals)
__device__ float g_qkv[(size_t)M_ROWS * N_QKV];   // [8192, 2304]
__device__ float g_y[(size_t)M_ROWS * C_DIM];     // [8192, 768]

// ---------------------------------------------------------------------------
// TF32 helpers
// ---------------------------------------------------------------------------
__device__ __forceinline__ uint32_t f2tf32(float x) {
    uint32_t r;
    asm("cvt.rna.tf32.f32 %0, %1;" : "=r"(r) : "f"(x));
    return r;
}

__device__ __forceinline__ void mma_tf32(float c[4],
                                         uint32_t a0, uint32_t a1,
                                         uint32_t a2, uint32_t a3,
                                         uint32_t b0, uint32_t b1) {
    asm volatile(
        "mma.sync.aligned.m16n8k8.row.col.f32.tf32.tf32.f32 "
        "{%0,%1,%2,%3}, {%4,%5,%6,%7}, {%8,%9}, {%0,%1,%2,%3};\n"
        : "+f"(c[0]), "+f"(c[1]), "+f"(c[2]), "+f"(c[3])
        : "r"(a0), "r"(a1), "r"(a2), "r"(a3), "r"(b0), "r"(b1));
}

// ---------------------------------------------------------------------------
// TF32 tensor-core GEMM with bias: C[M,N] = A[M,K] * B[K,N] + bias[N]
// BM=BN=128, BK=16. 128 threads = 4 warps (2x2), warp tile 64x64.
// Per k=8 step each warp feeds 32 MMAs from 32 LDS words (1.0 word/MMA).
// ---------------------------------------------------------------------------
__global__ __launch_bounds__(128, 2)
void gemm_tf32_bias_kernel(const float* __restrict__ A,
                           const float* __restrict__ B,
                           const float* __restrict__ bias,
                           float* __restrict__ C,
                           int M, int N, int K)
{
    constexpr int BM = 128, BN = 128, BK = 16;
    constexpr int LDS_ = 136;   // word stride -> conflict-free frag LDS

    __shared__ uint32_t As[BK][LDS_];   // [k][m], tf32 bits
    __shared__ uint32_t Bs[BK][LDS_];   // [k][n], tf32 bits

    const int tid  = threadIdx.x;            // 0..127
    const int brow = blockIdx.y;
    const int bcol = blockIdx.x;

    const int warp = tid >> 5;               // 0..3
    const int lane = tid & 31;
    const int g    = lane >> 2;              // 0..7
    const int t    = lane & 3;               // 0..3
    const int wm   = (warp & 1) * 64;        // warp m offset
    const int wn   = (warp >> 1) * 64;       // warp n offset

    const float* Ablk = A + (size_t)brow * BM * K;
    const float* Bblk = B + (size_t)bcol * BN;

    // gmem load mapping (128 threads cover 128x16 A and 16x128 B per tile)
    const int a_row = tid >> 2;              // 0..31 (rows +0,+32,+64,+96)
    const int a_col = (tid & 3) * 4;         // 0,4,8,12
    const int b_row = tid >> 5;              // 0..3 (rows +0,+4,+8,+12)
    const int b_col = (tid & 31) * 4;        // 0..124

    float acc[4][8][4];                      // [mt][nt][frag]
    #pragma unroll
    for (int mt = 0; mt < 4; mt++)
        #pragma unroll
        for (int nt = 0; nt < 8; nt++)
            #pragma unroll
            for (int i = 0; i < 4; i++)
                acc[mt][nt][i] = 0.0f;

    // Prefetch first tile
    float4 av[4], bv[4];
    #pragma unroll
    for (int rb = 0; rb < 4; rb++) {
        av[rb] = *(const float4*)(Ablk + (size_t)(a_row + rb * 32) * K + a_col);
        bv[rb] = *(const float4*)(Bblk + (size_t)(b_row + rb * 4) * N + b_col);
    }

    for (int k0 = 0; k0 < K; k0 += BK) {
        // Commit prefetch to smem (A transposed to [k][m]), converting to tf32
        #pragma unroll
        for (int rb = 0; rb < 4; rb++) {
            const int m = a_row + rb * 32;
            As[a_col + 0][m] = f2tf32(av[rb].x);
            As[a_col + 1][m] = f2tf32(av[rb].y);
            As[a_col + 2][m] = f2tf32(av[rb].z);
            As[a_col + 3][m] = f2tf32(av[rb].w);
            uint4 bw;
            bw.x = f2tf32(bv[rb].x);
            bw.y = f2tf32(bv[rb].y);
            bw.z = f2tf32(bv[rb].z);
            bw.w = f2tf32(bv[rb].w);
            *(uint4*)&Bs[b_row + rb * 4][b_col] = bw;
        }
        __syncthreads();

        // Prefetch next tile during MMA work
        const int kn = k0 + BK;
        if (kn < K) {
            #pragma unroll
            for (int rb = 0; rb < 4; rb++) {
                av[rb] = *(const float4*)(Ablk + (size_t)(a_row + rb * 32) * K + kn + a_col);
                bv[rb] = *(const float4*)(Bblk + (size_t)(kn + b_row + rb * 4) * N + b_col);
            }
        }

        // Two k-steps of 8
        #pragma unroll
        for (int ks = 0; ks < BK; ks += 8) {
            uint32_t a[4][4], bf[8][2];
            #pragma unroll
            for (int mt = 0; mt < 4; mt++) {
                const int m = wm + mt * 16 + g;
                a[mt][0] = As[ks + t][m];
                a[mt][1] = As[ks + t][m + 8];
                a[mt][2] = As[ks + t + 4][m];
                a[mt][3] = As[ks + t + 4][m + 8];
            }
            #pragma unroll
            for (int nt = 0; nt < 8; nt++) {
                const int n = wn + nt * 8 + g;
                bf[nt][0] = Bs[ks + t][n];
                bf[nt][1] = Bs[ks + t + 4][n];
            }
            #pragma unroll
            for (int mt = 0; mt < 4; mt++)
                #pragma unroll
                for (int nt = 0; nt < 8; nt++)
                    mma_tf32(acc[mt][nt],
                             a[mt][0], a[mt][1], a[mt][2], a[mt][3],
                             bf[nt][0], bf[nt][1]);
        }
        __syncthreads();
    }

    // Epilogue: bias + store
    #pragma unroll
    for (int mt = 0; mt < 4; mt++) {
        const size_t row0 = (size_t)brow * BM + wm + mt * 16 + g;
        #pragma unroll
        for (int nt = 0; nt < 8; nt++) {
            const int col = bcol * BN + wn + nt * 8 + 2 * t;
            const float bx = bias[col];
            const float by = bias[col + 1];
            float2 v0 = make_float2(acc[mt][nt][0] + bx, acc[mt][nt][1] + by);
            float2 v1 = make_float2(acc[mt][nt][2] + bx, acc[mt][nt][3] + by);
            *(float2*)(C + row0 * N + col)       = v0;
            *(float2*)(C + (row0 + 8) * N + col) = v1;
        }
    }
}

// ---------------------------------------------------------------------------
// Tensor-core causal flash attention (TF32 m16n8k8). Unchanged from round 6.
// ---------------------------------------------------------------------------
#define SQ 68
#define SV 72
#define ATT_SMEM_BYTES ((64 * SQ * 3 + 64 * SV) * 4)   // 70656

__global__ __launch_bounds__(128)
void attn_mma_kernel(const float* __restrict__ qkv, float* __restrict__ y)
{
    extern __shared__ uint32_t sm[];
    uint32_t* Qs = sm;                   // [64][SQ]
    uint32_t* Ks = Qs + 64 * SQ;         // [64][SQ]
    uint32_t* Vs = Ks + 64 * SQ;         // [64][SV]
    uint32_t* Ps = Vs + 64 * SV;         // [64][SQ]

    const int bh    = blockIdx.y;                    // 0..95
    const int b     = bh / H_NUM;
    const int h     = bh % H_NUM;
    const int qtile = (gridDim.x - 1) - blockIdx.x;  // heavy tiles first
    const int tid   = threadIdx.x;
    const int warp  = tid >> 5;
    const int lane  = tid & 31;
    const int g     = lane >> 2;                     // 0..7
    const int t     = lane & 3;                      // 0..3
    const int q0    = qtile * 64;

    const float* base = qkv + (size_t)b * T_SEQ * N_QKV + h * D_DIM;

    // Load Q tile (pre-scaled; 0.125 is a power of two -> lossless in tf32)
    for (int idx = tid; idx < 64 * 16; idx += 128) {
        const int r  = idx >> 4;
        const int c4 = (idx & 15) * 4;
        float4 v = *(const float4*)(base + (size_t)(q0 + r) * N_QKV + c4);
        Qs[r * SQ + c4 + 0] = f2tf32(v.x * SOFTMAX_SCALE);
        Qs[r * SQ + c4 + 1] = f2tf32(v.y * SOFTMAX_SCALE);
        Qs[r * SQ + c4 + 2] = f2tf32(v.z * SOFTMAX_SCALE);
        Qs[r * SQ + c4 + 3] = f2tf32(v.w * SOFTMAX_SCALE);
    }

    const int qr = warp * 16;       // warp's first local q row
    const int qa = q0 + qr + g;     // global query row (fragment row 0)
    const int qb = qa + 8;          // global query row (fragment row 1)

    float m0 = -1e30f, m1 = -1e30f, l0 = 0.0f, l1 = 0.0f;
    float O[8][4];
    #pragma unroll
    for (int n = 0; n < 8; n++)
        #pragma unroll
        for (int i = 0; i < 4; i++)
            O[n][i] = 0.0f;

    for (int kt = 0; kt <= qtile; kt++) {
        __syncthreads();
        // Load K/V tiles (natural [key][d] layout, converted to tf32)
        const float* kbase = base + (size_t)kt * 64 * N_QKV;
        for (int idx = tid; idx < 64 * 16; idx += 128) {
            const int r  = idx >> 4;
            const int c4 = (idx & 15) * 4;
            float4 kv = *(const float4*)(kbase + (size_t)r * N_QKV + C_DIM + c4);
            float4 vv = *(const float4*)(kbase + (size_t)r * N_QKV + 2 * C_DIM + c4);
            Ks[r * SQ + c4 + 0] = f2tf32(kv.x);
            Ks[r * SQ + c4 + 1] = f2tf32(kv.y);
            Ks[r * SQ + c4 + 2] = f2tf32(kv.z);
            Ks[r * SQ + c4 + 3] = f2tf32(kv.w);
            Vs[r * SV + c4 + 0] = f2tf32(vv.x);
            Vs[r * SV + c4 + 1] = f2tf32(vv.y);
            Vs[r * SV + c4 + 2] = f2tf32(vv.z);
            Vs[r * SV + c4 + 3] = f2tf32(vv.w);
        }
        __syncthreads();

        // S = Q * K^T   (16x64 per warp; accumulate over D in 8 k-steps)
        float s[8][4];
        #pragma unroll
        for (int n = 0; n < 8; n++)
            #pragma unroll
            for (int i = 0; i < 4; i++)
                s[n][i] = 0.0f;

        #pragma unroll
        for (int ks = 0; ks < 8; ks++) {
            const uint32_t a0 = Qs[(qr + g)     * SQ + ks * 8 + t];
            const uint32_t a1 = Qs[(qr + g + 8) * SQ + ks * 8 + t];
            const uint32_t a2 = Qs[(qr + g)     * SQ + ks * 8 + t + 4];
            const uint32_t a3 = Qs[(qr + g + 8) * SQ + ks * 8 + t + 4];
            #pragma unroll
            for (int nt = 0; nt < 8; nt++) {
                // B = K^T: element (k=d, n=key) = Ks[key][d]
                const uint32_t b0 = Ks[(nt * 8 + g) * SQ + ks * 8 + t];
                const uint32_t b1 = Ks[(nt * 8 + g) * SQ + ks * 8 + t + 4];
                mma_tf32(s[nt], a0, a1, a2, a3, b0, b1);
            }
        }

        // Causal mask (only the diagonal tile)
        if (kt == qtile) {
            #pragma unroll
            for (int nt = 0; nt < 8; nt++) {
                const int kc = kt * 64 + nt * 8 + 2 * t;
                if (kc     > qa) s[nt][0] = -1e30f;
                if (kc + 1 > qa) s[nt][1] = -1e30f;
                if (kc     > qb) s[nt][2] = -1e30f;
                if (kc + 1 > qb) s[nt][3] = -1e30f;
            }
        }

        // Online softmax: row maxima (quad-reduce), rescale, exp, write P
        float mc0 = -1e30f, mc1 = -1e30f;
        #pragma unroll
        for (int nt = 0; nt < 8; nt++) {
            mc0 = fmaxf(mc0, fmaxf(s[nt][0], s[nt][1]));
            mc1 = fmaxf(mc1, fmaxf(s[nt][2], s[nt][3]));
        }
        mc0 = fmaxf(mc0, __shfl_xor_sync(0xffffffffu, mc0, 1));
        mc0 = fmaxf(mc0, __shfl_xor_sync(0xffffffffu, mc0, 2));
        mc1 = fmaxf(mc1, __shfl_xor_sync(0xffffffffu, mc1, 1));
        mc1 = fmaxf(mc1, __shfl_xor_sync(0xffffffffu, mc1, 2));

        const float mn0 = fmaxf(m0, mc0);
        const float mn1 = fmaxf(m1, mc1);
        const float cr0 = __expf(m0 - mn0);
        const float cr1 = __expf(m1 - mn1);
        m0 = mn0; m1 = mn1;

        float pl0 = 0.0f, pl1 = 0.0f;
        #pragma unroll
        for (int nt = 0; nt < 8; nt++) {
            const float p0 = __expf(s[nt][0] - m0);
            const float p1 = __expf(s[nt][1] - m0);
            const float p2 = __expf(s[nt][2] - m1);
            const float p3 = __expf(s[nt][3] - m1);
            pl0 += p0 + p1;
            pl1 += p2 + p3;
            const int col = nt * 8 + 2 * t;
            Ps[(qr + g)     * SQ + col]     = f2tf32(p0);
            Ps[(qr + g)     * SQ + col + 1] = f2tf32(p1);
            Ps[(qr + g + 8) * SQ + col]     = f2tf32(p2);
            Ps[(qr + g + 8) * SQ + col + 1] = f2tf32(p3);
        }
        // Reduce the row sums across the quad
        pl0 += __shfl_xor_sync(0xffffffffu, pl0, 1);
        pl0 += __shfl_xor_sync(0xffffffffu, pl0, 2);
        pl1 += __shfl_xor_sync(0xffffffffu, pl1, 1);
        pl1 += __shfl_xor_sync(0xffffffffu, pl1, 2);

        l0 = l0 * cr0 + pl0;
        l1 = l1 * cr1 + pl1;
        #pragma unroll
        for (int n = 0; n < 8; n++) {
            O[n][0] *= cr0; O[n][1] *= cr0;
            O[n][2] *= cr1; O[n][3] *= cr1;
        }
        __syncwarp();   // P rows are warp-private; quad cross-reads below

        // O += P * V  (k-dim = keys, 8 k-steps)
        #pragma unroll
        for (int ks = 0; ks < 8; ks++) {
            const uint32_t a0 = Ps[(qr + g)     * SQ + ks * 8 + t];
            const uint32_t a1 = Ps[(qr + g + 8) * SQ + ks * 8 + t];
            const uint32_t a2 = Ps[(qr + g)     * SQ + ks * 8 + t + 4];
            const uint32_t a3 = Ps[(qr + g + 8) * SQ + ks * 8 + t + 4];
            #pragma unroll
            for (int nt2 = 0; nt2 < 8; nt2++) {
                const uint32_t b0 = Vs[(ks * 8 + t)     * SV + nt2 * 8 + g];
                const uint32_t b1 = Vs[(ks * 8 + t + 4) * SV + nt2 * 8 + g];
                mma_tf32(O[nt2], a0, a1, a2, a3, b0, b1);
            }
        }
    }

    // Epilogue: normalize and store
    const float i0 = 1.0f / l0;
    const float i1 = 1.0f / l1;
    float* ya = y + ((size_t)b * T_SEQ + qa) * C_DIM + h * D_DIM;
    float* yb = y + ((size_t)b * T_SEQ + qb) * C_DIM + h * D_DIM;
    #pragma unroll
    for (int nt2 = 0; nt2 < 8; nt2++) {
        const int d = nt2 * 8 + 2 * t;
        *(float2*)(ya + d) = make_float2(O[nt2][0] * i0, O[nt2][1] * i0);
        *(float2*)(yb + d) = make_float2(O[nt2][2] * i1, O[nt2][3] * i1);
    }
}

// ---------------------------------------------------------------------------
// Launch
// ---------------------------------------------------------------------------
extern "C" void kernel_launch(void* const* d_in, const int* in_sizes, int n_in,
                              void* d_out, int out_size)
{
    const float* x      = (const float*)d_in[0];   // [8, 1024, 768]
    const float* W_attn = (const float*)d_in[1];   // [768, 2304]
    const float* b_attn = (const float*)d_in[2];   // [2304]
    const float* W_proj = (const float*)d_in[3];   // [768, 768]
    const float* b_proj = (const float*)d_in[4];   // [768]
    float* out = (float*)d_out;                    // [8, 1024, 768]

    float* qkv;  cudaGetSymbolAddress((void**)&qkv, g_qkv);
    float* ybuf; cudaGetSymbolAddress((void**)&ybuf, g_y);

    cudaFuncSetAttribute(attn_mma_kernel,
                         cudaFuncAttributeMaxDynamicSharedMemorySize,
                         ATT_SMEM_BYTES);

    // 1) QKV GEMM (TF32 tensor cores): [8192,768] x [768,2304] + bias
    {
        dim3 grid(N_QKV / 128, M_ROWS / 128);   // (18, 64)
        gemm_tf32_bias_kernel<<<grid, 128>>>(x, W_attn, b_attn, qkv,
                                             M_ROWS, N_QKV, C_DIM);
    }
    // 2) Causal flash attention (TF32 tensor cores)
    {
        dim3 grid(T_SEQ / 64, B_SZ * H_NUM);    // (16, 96)
        attn_mma_kernel<<<grid, 128, ATT_SMEM_BYTES>>>(qkv, ybuf);
    }
    // 3) Projection GEMM (TF32 tensor cores): [8192,768] x [768,768] + bias
    {
        dim3 grid(C_DIM / 128, M_ROWS / 128);   // (6, 64)
        gemm_tf32_bias_kernel<<<grid, 128>>>(ybuf, W_proj, b_proj, out,
                                             M_ROWS, C_DIM, C_DIM);
    }
}

// round 8
// speedup vs baseline: 4.7423x; 1.0596x over previous
#include <cuda_runtime.h>
#include <cstdint>

// Problem constants
#define B_SZ   8
#define T_SEQ  1024
#define C_DIM  768
#define H_NUM  12
#define D_DIM  64
#define M_ROWS (B_SZ * T_SEQ)          // 8192
#define N_QKV  (3 * C_DIM)             // 2304
#define SOFTMAX_SCALE 0.125f           // 1/sqrt(64), exact power of two

// Scratch (allocation-free rule: __device__ globals)
__device__ float g_qkv[(size_t)M_ROWS * N_QKV];   // [8192, 2304]
__device__ float g_y[(size_t)M_ROWS * C_DIM];     // [8192, 768] (tf32-rounded)
__device__ float g_xr[(size_t)M_ROWS * C_DIM];    // tf32-rounded x
__device__ float g_War[(size_t)C_DIM * N_QKV];    // tf32-rounded W_attn
__device__ float g_Wpr[(size_t)C_DIM * C_DIM];    // tf32-rounded W_proj

// ---------------------------------------------------------------------------
// TF32 helpers
// ---------------------------------------------------------------------------
__device__ __forceinline__ uint32_t f2tf32(float x) {
    uint32_t r;
    asm("cvt.rna.tf32.f32 %0, %1;" : "=r"(r) : "f"(x));
    return r;
}

__device__ __forceinline__ void mma_tf32(float c[4],
                                         uint32_t a0, uint32_t a1,
                                         uint32_t a2, uint32_t a3,
                                         uint32_t b0, uint32_t b1) {
    asm volatile(
        "mma.sync.aligned.m16n8k8.row.col.f32.tf32.tf32.f32 "
        "{%0,%1,%2,%3}, {%4,%5,%6,%7}, {%8,%9}, {%0,%1,%2,%3};\n"
        : "+f"(c[0]), "+f"(c[1]), "+f"(c[2]), "+f"(c[3])
        : "r"(a0), "r"(a1), "r"(a2), "r"(a3), "r"(b0), "r"(b1));
}

__device__ __forceinline__ void cp_async16(uint32_t saddr, const void* gptr) {
    asm volatile("cp.async.cg.shared.global [%0], [%1], 16;\n"
                 :: "r"(saddr), "l"(gptr));
}
__device__ __forceinline__ void cp_commit() {
    asm volatile("cp.async.commit_group;\n");
}
template <int N>
__device__ __forceinline__ void cp_wait() {
    asm volatile("cp.async.wait_group %0;\n" :: "n"(N));
}

// ---------------------------------------------------------------------------
// Elementwise tf32 RNA pre-rounding: dst[i] = round_tf32(src[i]) (fp32 bits)
// ---------------------------------------------------------------------------
__global__ void round_tf32_kernel(const float* __restrict__ src,
                                  float* __restrict__ dst, int n4)
{
    const int i = blockIdx.x * blockDim.x + threadIdx.x;
    if (i < n4) {
        float4 v = *(const float4*)(src + (size_t)i * 4);
        uint4 r;
        r.x = f2tf32(v.x); r.y = f2tf32(v.y);
        r.z = f2tf32(v.z); r.w = f2tf32(v.w);
        *(uint4*)(dst + (size_t)i * 4) = r;
    }
}

// ---------------------------------------------------------------------------
// TF32 tensor-core GEMM with bias: C[M,N] = A[M,K] * B[K,N] + bias[N]
// Inputs A, B MUST be pre-rounded to tf32 (low mantissa bits zero).
// BM=BN=128, BK=16, 128 threads (4 warps, 2x2), warp tile 64x64.
// 3-stage cp.async pipeline, one __syncthreads per K-tile, zero cvt in loop.
// smem: A [128][20] words (natural [m][k], stride 20 -> conflict-free frags),
//       B [16][136] words ([k][n], stride 136 -> conflict-free frags).
// ---------------------------------------------------------------------------
#define GA_W  (128 * 20)               // A stage words
#define GB_W  (16 * 136)               // B stage words
#define GEMM_SMEM_BYTES (3 * (GA_W + GB_W) * 4)   // 56832

__global__ __launch_bounds__(128, 2)
void gemm_tf32_bias_kernel(const float* __restrict__ A,
                           const float* __restrict__ B,
                           const float* __restrict__ bias,
                           float* __restrict__ C,
                           int M, int N, int K)
{
    constexpr int BM = 128, BN = 128, BK = 16;

    extern __shared__ uint32_t smg[];

    const int tid  = threadIdx.x;            // 0..127
    const int brow = blockIdx.y;
    const int bcol = blockIdx.x;

    const int warp = tid >> 5;               // 0..3
    const int lane = tid & 31;
    const int g    = lane >> 2;              // 0..7
    const int t    = lane & 3;               // 0..3
    const int wm   = (warp & 1) * 64;
    const int wn   = (warp >> 1) * 64;

    const float* Ablk = A + (size_t)brow * BM * K;
    const float* Bblk = B + (size_t)bcol * BN;

    // cp.async mapping: A 128x16 words = 512 chunks of 16B, 4 per thread
    const int a_row = tid >> 2;              // 0..31 (+0,+32,+64,+96)
    const int a_col = (tid & 3) * 4;         // 0,4,8,12
    // B 16x128 words = 512 chunks, 4 per thread
    const int b_row = tid >> 5;              // 0..3 (+0,+4,+8,+12)
    const int b_col = (tid & 31) * 4;        // 0..124

    uint32_t sbase;
    {
        void* p = (void*)smg;
        sbase = (uint32_t)__cvta_generic_to_shared(p);
    }

    const int ntiles = K / BK;               // 48 or 48

    // Issue one stage's copies
    auto issue_stage = [&](int tile, int stage) {
        const uint32_t as = sbase + (uint32_t)(stage * (GA_W + GB_W)) * 4;
        const uint32_t bs = as + GA_W * 4;
        const int k0 = tile * BK;
        #pragma unroll
        for (int rb = 0; rb < 4; rb++) {
            const int m = a_row + rb * 32;
            cp_async16(as + (uint32_t)(m * 20 + a_col) * 4,
                       Ablk + (size_t)m * K + k0 + a_col);
            const int kr = b_row + rb * 4;
            cp_async16(bs + (uint32_t)(kr * 136 + b_col) * 4,
                       Bblk + (size_t)(k0 + kr) * N + b_col);
        }
        cp_commit();
    };

    float acc[4][8][4];                      // [mt][nt][frag]
    #pragma unroll
    for (int mt = 0; mt < 4; mt++)
        #pragma unroll
        for (int nt = 0; nt < 8; nt++)
            #pragma unroll
            for (int i = 0; i < 4; i++)
                acc[mt][nt][i] = 0.0f;

    // Prologue: stages 0 and 1 in flight
    issue_stage(0, 0);
    issue_stage(1, 1);

    int stage = 0;
    for (int i = 0; i < ntiles; i++) {
        if (i + 1 < ntiles) cp_wait<1>(); else cp_wait<0>();
        __syncthreads();

        const uint32_t* As = smg + stage * (GA_W + GB_W);          // [m][20]
        const uint32_t* Bs = As + GA_W;                            // [k][136]

        #pragma unroll
        for (int ks = 0; ks < BK; ks += 8) {
            uint32_t a[4][4], bf[8][2];
            #pragma unroll
            for (int mt = 0; mt < 4; mt++) {
                const int m = wm + mt * 16 + g;
                a[mt][0] = As[m * 20 + ks + t];
                a[mt][1] = As[(m + 8) * 20 + ks + t];
                a[mt][2] = As[m * 20 + ks + t + 4];
                a[mt][3] = As[(m + 8) * 20 + ks + t + 4];
            }
            #pragma unroll
            for (int nt = 0; nt < 8; nt++) {
                const int n = wn + nt * 8 + g;
                bf[nt][0] = Bs[(ks + t) * 136 + n];
                bf[nt][1] = Bs[(ks + t + 4) * 136 + n];
            }
            #pragma unroll
            for (int mt = 0; mt < 4; mt++)
                #pragma unroll
                for (int nt = 0; nt < 8; nt++)
                    mma_tf32(acc[mt][nt],
                             a[mt][0], a[mt][1], a[mt][2], a[mt][3],
                             bf[nt][0], bf[nt][1]);
        }

        // Refill the stage we just freed (i+2), guarded by this tile's sync
        if (i + 2 < ntiles) issue_stage(i + 2, (stage + 2) % 3);
        stage = (stage + 1) % 3;
    }

    // Epilogue: bias + store
    #pragma unroll
    for (int mt = 0; mt < 4; mt++) {
        const size_t row0 = (size_t)brow * BM + wm + mt * 16 + g;
        #pragma unroll
        for (int nt = 0; nt < 8; nt++) {
            const int col = bcol * BN + wn + nt * 8 + 2 * t;
            const float bx = bias[col];
            const float by = bias[col + 1];
            float2 v0 = make_float2(acc[mt][nt][0] + bx, acc[mt][nt][1] + by);
            float2 v1 = make_float2(acc[mt][nt][2] + bx, acc[mt][nt][3] + by);
            *(float2*)(C + row0 * N + col)       = v0;
            *(float2*)(C + (row0 + 8) * N + col) = v1;
        }
    }
}

// ---------------------------------------------------------------------------
// Tensor-core causal flash attention (TF32 m16n8k8).
// Unchanged except: epilogue stores tf32-rounded y (feeds proj GEMM directly).
// ---------------------------------------------------------------------------
#define SQ 68
#define SV 72
#define ATT_SMEM_BYTES ((64 * SQ * 3 + 64 * SV) * 4)   // 70656

__global__ __launch_bounds__(128)
void attn_mma_kernel(const float* __restrict__ qkv, float* __restrict__ y)
{
    extern __shared__ uint32_t sm[];
    uint32_t* Qs = sm;                   // [64][SQ]
    uint32_t* Ks = Qs + 64 * SQ;         // [64][SQ]
    uint32_t* Vs = Ks + 64 * SQ;         // [64][SV]
    uint32_t* Ps = Vs + 64 * SV;         // [64][SQ]

    const int bh    = blockIdx.y;                    // 0..95
    const int b     = bh / H_NUM;
    const int h     = bh % H_NUM;
    const int qtile = (gridDim.x - 1) - blockIdx.x;  // heavy tiles first
    const int tid   = threadIdx.x;
    const int warp  = tid >> 5;
    const int lane  = tid & 31;
    const int g     = lane >> 2;                     // 0..7
    const int t     = lane & 3;                      // 0..3
    const int q0    = qtile * 64;

    const float* base = qkv + (size_t)b * T_SEQ * N_QKV + h * D_DIM;

    // Load Q tile (pre-scaled; 0.125 is a power of two -> lossless in tf32)
    for (int idx = tid; idx < 64 * 16; idx += 128) {
        const int r  = idx >> 4;
        const int c4 = (idx & 15) * 4;
        float4 v = *(const float4*)(base + (size_t)(q0 + r) * N_QKV + c4);
        Qs[r * SQ + c4 + 0] = f2tf32(v.x * SOFTMAX_SCALE);
        Qs[r * SQ + c4 + 1] = f2tf32(v.y * SOFTMAX_SCALE);
        Qs[r * SQ + c4 + 2] = f2tf32(v.z * SOFTMAX_SCALE);
        Qs[r * SQ + c4 + 3] = f2tf32(v.w * SOFTMAX_SCALE);
    }

    const int qr = warp * 16;       // warp's first local q row
    const int qa = q0 + qr + g;     // global query row (fragment row 0)
    const int qb = qa + 8;          // global query row (fragment row 1)

    float m0 = -1e30f, m1 = -1e30f, l0 = 0.0f, l1 = 0.0f;
    float O[8][4];
    #pragma unroll
    for (int n = 0; n < 8; n++)
        #pragma unroll
        for (int i = 0; i < 4; i++)
            O[n][i] = 0.0f;

    for (int kt = 0; kt <= qtile; kt++) {
        __syncthreads();
        // Load K/V tiles (natural [key][d] layout, converted to tf32)
        const float* kbase = base + (size_t)kt * 64 * N_QKV;
        for (int idx = tid; idx < 64 * 16; idx += 128) {
            const int r  = idx >> 4;
            const int c4 = (idx & 15) * 4;
            float4 kv = *(const float4*)(kbase + (size_t)r * N_QKV + C_DIM + c4);
            float4 vv = *(const float4*)(kbase + (size_t)r * N_QKV + 2 * C_DIM + c4);
            Ks[r * SQ + c4 + 0] = f2tf32(kv.x);
            Ks[r * SQ + c4 + 1] = f2tf32(kv.y);
            Ks[r * SQ + c4 + 2] = f2tf32(kv.z);
            Ks[r * SQ + c4 + 3] = f2tf32(kv.w);
            Vs[r * SV + c4 + 0] = f2tf32(vv.x);
            Vs[r * SV + c4 + 1] = f2tf32(vv.y);
            Vs[r * SV + c4 + 2] = f2tf32(vv.z);
            Vs[r * SV + c4 + 3] = f2tf32(vv.w);
        }
        __syncthreads();

        // S = Q * K^T
        float s[8][4];
        #pragma unroll
        for (int n = 0; n < 8; n++)
            #pragma unroll
            for (int i = 0; i < 4; i++)
                s[n][i] = 0.0f;

        #pragma unroll
        for (int ks = 0; ks < 8; ks++) {
            const uint32_t a0 = Qs[(qr + g)     * SQ + ks * 8 + t];
            const uint32_t a1 = Qs[(qr + g + 8) * SQ + ks * 8 + t];
            const uint32_t a2 = Qs[(qr + g)     * SQ + ks * 8 + t + 4];
            const uint32_t a3 = Qs[(qr + g + 8) * SQ + ks * 8 + t + 4];
            #pragma unroll
            for (int nt = 0; nt < 8; nt++) {
                const uint32_t b0 = Ks[(nt * 8 + g) * SQ + ks * 8 + t];
                const uint32_t b1 = Ks[(nt * 8 + g) * SQ + ks * 8 + t + 4];
                mma_tf32(s[nt], a0, a1, a2, a3, b0, b1);
            }
        }

        // Causal mask (only the diagonal tile)
        if (kt == qtile) {
            #pragma unroll
            for (int nt = 0; nt < 8; nt++) {
                const int kc = kt * 64 + nt * 8 + 2 * t;
                if (kc     > qa) s[nt][0] = -1e30f;
                if (kc + 1 > qa) s[nt][1] = -1e30f;
                if (kc     > qb) s[nt][2] = -1e30f;
                if (kc + 1 > qb) s[nt][3] = -1e30f;
            }
        }

        // Online softmax
        float mc0 = -1e30f, mc1 = -1e30f;
        #pragma unroll
        for (int nt = 0; nt < 8; nt++) {
            mc0 = fmaxf(mc0, fmaxf(s[nt][0], s[nt][1]));
            mc1 = fmaxf(mc1, fmaxf(s[nt][2], s[nt][3]));
        }
        mc0 = fmaxf(mc0, __shfl_xor_sync(0xffffffffu, mc0, 1));
        mc0 = fmaxf(mc0, __shfl_xor_sync(0xffffffffu, mc0, 2));
        mc1 = fmaxf(mc1, __shfl_xor_sync(0xffffffffu, mc1, 1));
        mc1 = fmaxf(mc1, __shfl_xor_sync(0xffffffffu, mc1, 2));

        const float mn0 = fmaxf(m0, mc0);
        const float mn1 = fmaxf(m1, mc1);
        const float cr0 = __expf(m0 - mn0);
        const float cr1 = __expf(m1 - mn1);
        m0 = mn0; m1 = mn1;

        float pl0 = 0.0f, pl1 = 0.0f;
        #pragma unroll
        for (int nt = 0; nt < 8; nt++) {
            const float p0 = __expf(s[nt][0] - m0);
            const float p1 = __expf(s[nt][1] - m0);
            const float p2 = __expf(s[nt][2] - m1);
            const float p3 = __expf(s[nt][3] - m1);
            pl0 += p0 + p1;
            pl1 += p2 + p3;
            const int col = nt * 8 + 2 * t;
            Ps[(qr + g)     * SQ + col]     = f2tf32(p0);
            Ps[(qr + g)     * SQ + col + 1] = f2tf32(p1);
            Ps[(qr + g + 8) * SQ + col]     = f2tf32(p2);
            Ps[(qr + g + 8) * SQ + col + 1] = f2tf32(p3);
        }
        pl0 += __shfl_xor_sync(0xffffffffu, pl0, 1);
        pl0 += __shfl_xor_sync(0xffffffffu, pl0, 2);
        pl1 += __shfl_xor_sync(0xffffffffu, pl1, 1);
        pl1 += __shfl_xor_sync(0xffffffffu, pl1, 2);

        l0 = l0 * cr0 + pl0;
        l1 = l1 * cr1 + pl1;
        #pragma unroll
        for (int n = 0; n < 8; n++) {
            O[n][0] *= cr0; O[n][1] *= cr0;
            O[n][2] *= cr1; O[n][3] *= cr1;
        }
        __syncwarp();

        // O += P * V
        #pragma unroll
        for (int ks = 0; ks < 8; ks++) {
            const uint32_t a0 = Ps[(qr + g)     * SQ + ks * 8 + t];
            const uint32_t a1 = Ps[(qr + g + 8) * SQ + ks * 8 + t];
            const uint32_t a2 = Ps[(qr + g)     * SQ + ks * 8 + t + 4];
            const uint32_t a3 = Ps[(qr + g + 8) * SQ + ks * 8 + t + 4];
            #pragma unroll
            for (int nt2 = 0; nt2 < 8; nt2++) {
                const uint32_t b0 = Vs[(ks * 8 + t)     * SV + nt2 * 8 + g];
                const uint32_t b1 = Vs[(ks * 8 + t + 4) * SV + nt2 * 8 + g];
                mma_tf32(O[nt2], a0, a1, a2, a3, b0, b1);
            }
        }
    }

    // Epilogue: normalize, tf32-round (proj GEMM input), and store
    const float i0 = 1.0f / l0;
    const float i1 = 1.0f / l1;
    float* ya = y + ((size_t)b * T_SEQ + qa) * C_DIM + h * D_DIM;
    float* yb = y + ((size_t)b * T_SEQ + qb) * C_DIM + h * D_DIM;
    #pragma unroll
    for (int nt2 = 0; nt2 < 8; nt2++) {
        const int d = nt2 * 8 + 2 * t;
        *(float2*)(ya + d) = make_float2(
            __uint_as_float(f2tf32(O[nt2][0] * i0)),
            __uint_as_float(f2tf32(O[nt2][1] * i0)));
        *(float2*)(yb + d) = make_float2(
            __uint_as_float(f2tf32(O[nt2][2] * i1)),
            __uint_as_float(f2tf32(O[nt2][3] * i1)));
    }
}

// ---------------------------------------------------------------------------
// Launch
// ---------------------------------------------------------------------------
extern "C" void kernel_launch(void* const* d_in, const int* in_sizes, int n_in,
                              void* d_out, int out_size)
{
    const float* x      = (const float*)d_in[0];   // [8, 1024, 768]
    const float* W_attn = (const float*)d_in[1];   // [768, 2304]
    const float* b_attn = (const float*)d_in[2];   // [2304]
    const float* W_proj = (const float*)d_in[3];   // [768, 768]
    const float* b_proj = (const float*)d_in[4];   // [768]
    float* out = (float*)d_out;                    // [8, 1024, 768]

    float* qkv;  cudaGetSymbolAddress((void**)&qkv, g_qkv);
    float* ybuf; cudaGetSymbolAddress((void**)&ybuf, g_y);
    float* xr;   cudaGetSymbolAddress((void**)&xr,  g_xr);
    float* War;  cudaGetSymbolAddress((void**)&War, g_War);
    float* Wpr;  cudaGetSymbolAddress((void**)&Wpr, g_Wpr);

    cudaFuncSetAttribute(attn_mma_kernel,
                         cudaFuncAttributeMaxDynamicSharedMemorySize,
                         ATT_SMEM_BYTES);
    cudaFuncSetAttribute(gemm_tf32_bias_kernel,
                         cudaFuncAttributeMaxDynamicSharedMemorySize,
                         GEMM_SMEM_BYTES);

    // 0) Pre-round inputs to tf32 (RNA), so GEMMs skip in-loop conversion
    {
        const int nx = M_ROWS * C_DIM / 4;
        const int na = C_DIM * N_QKV / 4;
        const int np = C_DIM * C_DIM / 4;
        round_tf32_kernel<<<(nx + 255) / 256, 256>>>(x, xr, nx);
        round_tf32_kernel<<<(na + 255) / 256, 256>>>(W_attn, War, na);
        round_tf32_kernel<<<(np + 255) / 256, 256>>>(W_proj, Wpr, np);
    }
    // 1) QKV GEMM (TF32 tensor cores, cp.async pipeline)
    {
        dim3 grid(N_QKV / 128, M_ROWS / 128);   // (18, 64)
        gemm_tf32_bias_kernel<<<grid, 128, GEMM_SMEM_BYTES>>>(
            xr, War, b_attn, qkv, M_ROWS, N_QKV, C_DIM);
    }
    // 2) Causal flash attention (TF32 tensor cores)
    {
        dim3 grid(T_SEQ / 64, B_SZ * H_NUM);    // (16, 96)
        attn_mma_kernel<<<grid, 128, ATT_SMEM_BYTES>>>(qkv, ybuf);
    }
    // 3) Projection GEMM (TF32 tensor cores, cp.async pipeline)
    {
        dim3 grid(C_DIM / 128, M_ROWS / 128);   // (6, 64)
        gemm_tf32_bias_kernel<<<grid, 128, GEMM_SMEM_BYTES>>>(
            ybuf, Wpr, b_proj, out, M_ROWS, C_DIM, C_DIM);
    }
}